// round 1
// baseline (speedup 1.0000x reference)
#include <cuda_runtime.h>
#include <math.h>

// Problem shape (fixed by the reference): x[4,2048,1024] @ W1[1024,4096] -> qt -> relu -> @ W2[4096,1024]
#define MTOK   8192      // B*S
#define DMODEL 1024
#define DFF    4096

#define BM 128
#define BN 128
#define BK 16
#define TM 8
#define TN 8
// threads = (BM/TM)*(BN/TN) = 16*16 = 256

// Scratch for the post-activation hidden state (128 MB). __device__ globals are the
// sanctioned scratch mechanism (no runtime allocation allowed).
__device__ float g_act[(size_t)MTOK * DFF];

// Tiled SGEMM: C[M,N] = A[M,K] @ B[K,N] + bias[N], with optional fused
// quantum-transform + ReLU epilogue (GEMM1 only).
template <bool FUSE_Q>
__global__ __launch_bounds__(256, 2)
void sgemm_kernel(const float* __restrict__ A,
                  const float* __restrict__ B,
                  const float* __restrict__ bias,
                  const float* __restrict__ theta,
                  const float* __restrict__ wre,
                  const float* __restrict__ wim,
                  float* __restrict__ C,
                  int M, int N, int K)
{
    __shared__ float As[BK][BM + 4];   // +4 pad: conflict-free transposed stores
    __shared__ float Bs[BK][BN];

    const int tid = threadIdx.x;          // 0..255
    const int tx  = tid & 15;             // output column group
    const int ty  = tid >> 4;             // output row group

    const int block_row = blockIdx.y;     // M tile index
    const int block_col = blockIdx.x;     // N tile index

    const float* A_tile = A + (size_t)block_row * BM * K;
    const float* B_tile = B + (size_t)block_col * BN;
    float*       C_tile = C + (size_t)block_row * BM * N + (size_t)block_col * BN;

    float acc[TM][TN];
#pragma unroll
    for (int i = 0; i < TM; i++)
#pragma unroll
        for (int j = 0; j < TN; j++) acc[i][j] = 0.0f;

    for (int k0 = 0; k0 < K; k0 += BK) {
        // ---- load A tile (BM x BK) as float4 along K, store transposed As[k][m] ----
        // 128 rows * 16 cols = 512 float4 loads; 2 per thread
#pragma unroll
        for (int i = 0; i < 2; i++) {
            int f   = tid + i * 256;        // 0..511
            int row = f >> 2;               // 0..127
            int c4  = (f & 3) << 2;         // 0,4,8,12
            float4 v = *(const float4*)(A_tile + (size_t)row * K + k0 + c4);
            As[c4 + 0][row] = v.x;
            As[c4 + 1][row] = v.y;
            As[c4 + 2][row] = v.z;
            As[c4 + 3][row] = v.w;
        }
        // ---- load B tile (BK x BN) as float4 along N, direct layout Bs[k][n] ----
        // 16 rows * 32 float4 = 512; 2 per thread
#pragma unroll
        for (int i = 0; i < 2; i++) {
            int f   = tid + i * 256;        // 0..511
            int row = f >> 5;               // 0..15
            int c4  = (f & 31) << 2;        // 0..124
            *(float4*)(&Bs[row][c4]) =
                *(const float4*)(B_tile + (size_t)(k0 + row) * N + c4);
        }
        __syncthreads();

        // ---- 8x8 outer-product accumulate over BK ----
#pragma unroll
        for (int k = 0; k < BK; k++) {
            float ra[TM], rb[TN];
            float4 a0 = *(const float4*)(&As[k][ty * TM + 0]);
            float4 a1 = *(const float4*)(&As[k][ty * TM + 4]);
            ra[0] = a0.x; ra[1] = a0.y; ra[2] = a0.z; ra[3] = a0.w;
            ra[4] = a1.x; ra[5] = a1.y; ra[6] = a1.z; ra[7] = a1.w;
            float4 b0 = *(const float4*)(&Bs[k][tx * TN + 0]);
            float4 b1 = *(const float4*)(&Bs[k][tx * TN + 4]);
            rb[0] = b0.x; rb[1] = b0.y; rb[2] = b0.z; rb[3] = b0.w;
            rb[4] = b1.x; rb[5] = b1.y; rb[6] = b1.z; rb[7] = b1.w;
#pragma unroll
            for (int i = 0; i < TM; i++)
#pragma unroll
                for (int j = 0; j < TN; j++)
                    acc[i][j] = fmaf(ra[i], rb[j], acc[i][j]);
        }
        __syncthreads();
    }

    // ---- epilogue: bias (+ quantum transform + relu for GEMM1) ----
#pragma unroll
    for (int j = 0; j < TN; j++) {
        const int n = block_col * BN + tx * TN + j;
        const float bj = bias[n];
        float th = 0.f, wij = 0.f, qp = 0.f;
        if (FUSE_Q) {
            th = theta[n];
            float s, c;
            sincosf(th, &s, &c);
            wij = wim[n];
            // quantum_phase * 0.1 folded together; depends only on channel n
            qp = (c * wre[n] + s * wij) * 0.1f;
        }
#pragma unroll
        for (int i = 0; i < TM; i++) {
            float h = acc[i][j] + bj;
            if (FUSE_Q) {
                float im = wij * sinf(th + h * 0.1f);
                h = fmaf(qp, im, h);
                h = fmaxf(h, 0.0f);
            }
            C_tile[(size_t)(ty * TM + i) * N + tx * TN + j] = h;
        }
    }
}

extern "C" void kernel_launch(void* const* d_in, const int* in_sizes, int n_in,
                              void* d_out, int out_size)
{
    const float* x   = (const float*)d_in[0];   // [8192,1024]
    const float* W1  = (const float*)d_in[1];   // [1024,4096]
    const float* b1  = (const float*)d_in[2];   // [4096]
    const float* th  = (const float*)d_in[3];   // [4096]
    const float* wre = (const float*)d_in[4];   // [4096]
    const float* wim = (const float*)d_in[5];   // [4096]
    const float* W2  = (const float*)d_in[6];   // [4096,1024]
    const float* b2  = (const float*)d_in[7];   // [1024]
    float* out = (float*)d_out;                 // [8192,1024]

    void* actp = nullptr;
    cudaGetSymbolAddress(&actp, g_act);         // query only; no allocation
    float* act = (float*)actp;

    // GEMM1: act = relu(qt(x @ W1 + b1))   [8192,4096]
    {
        dim3 grid(DFF / BN, MTOK / BM);         // (32, 64)
        sgemm_kernel<true><<<grid, 256>>>(x, W1, b1, th, wre, wim, act,
                                          MTOK, DFF, DMODEL);
    }
    // GEMM2: out = act @ W2 + b2           [8192,1024]
    {
        dim3 grid(DMODEL / BN, MTOK / BM);      // (8, 64)
        sgemm_kernel<false><<<grid, 256>>>(act, W2, b2, nullptr, nullptr, nullptr,
                                           out, MTOK, DMODEL, DFF);
    }
}

// round 3
// speedup vs baseline: 3.5366x; 3.5366x over previous
#include <cuda_runtime.h>
#include <cstdint>
#include <math.h>

#define MTOK   8192
#define DMODEL 1024
#define DFF    4096

// ---------------- scratch (device globals; no runtime allocation) ----------------
__device__ float g_xr [(size_t)MTOK * DMODEL];   // x rounded to tf32
__device__ float g_w1t[(size_t)DFF  * DMODEL];   // W1^T rounded  [N=4096][K=1024]
__device__ float g_w2t[(size_t)DMODEL * DFF];    // W2^T rounded  [N=1024][K=4096]
__device__ float g_act[(size_t)MTOK * DFF];      // post-activation hidden (tf32-rounded)
__device__ float g_qp [DFF];                     // (cos(th)*wre + sin(th)*wim)*0.1

// ---------------- helpers ----------------
__device__ __forceinline__ uint32_t smem_u32(const void* p) {
    uint32_t a;
    asm("{ .reg .u64 t; cvta.to.shared.u64 t, %1; cvt.u32.u64 %0, t; }" : "=r"(a) : "l"(p));
    return a;
}
__device__ __forceinline__ float tf32_rna(float x) {
    uint32_t r; asm("cvt.rna.tf32.f32 %0, %1;" : "=r"(r) : "f"(x));
    return __uint_as_float(r);
}
__device__ __forceinline__ void cp_async16(uint32_t saddr, const void* g) {
    asm volatile("cp.async.cg.shared.global [%0], [%1], 16;" :: "r"(saddr), "l"(g) : "memory");
}
__device__ __forceinline__ void ldsm_x4(uint32_t& r0, uint32_t& r1, uint32_t& r2, uint32_t& r3,
                                        uint32_t addr) {
    asm volatile("ldmatrix.sync.aligned.m8n8.x4.shared.b16 {%0,%1,%2,%3}, [%4];"
                 : "=r"(r0), "=r"(r1), "=r"(r2), "=r"(r3) : "r"(addr));
}
__device__ __forceinline__ void mma_tf32(float* c, const uint32_t* a, const uint32_t* b) {
    asm volatile(
        "mma.sync.aligned.m16n8k8.row.col.f32.tf32.tf32.f32 "
        "{%0,%1,%2,%3}, {%4,%5,%6,%7}, {%8,%9}, {%0,%1,%2,%3};"
        : "+f"(c[0]), "+f"(c[1]), "+f"(c[2]), "+f"(c[3])
        : "r"(a[0]), "r"(a[1]), "r"(a[2]), "r"(a[3]), "r"(b[0]), "r"(b[1]));
}
__device__ __forceinline__ uint32_t sw128(uint32_t bo) { return bo ^ ((bo >> 3) & 0x70); }

// ---------------- preprocessing kernels ----------------
__global__ void round_copy_k(const float* __restrict__ in, float* __restrict__ out, int n4) {
    int i = blockIdx.x * blockDim.x + threadIdx.x;
    if (i < n4) {
        float4 v = ((const float4*)in)[i];
        v.x = tf32_rna(v.x); v.y = tf32_rna(v.y); v.z = tf32_rna(v.z); v.w = tf32_rna(v.w);
        ((float4*)out)[i] = v;
    }
}
__global__ void transpose_round_k(const float* __restrict__ in, float* __restrict__ out,
                                  int R, int C) {
    __shared__ float t[32][33];
    int bx = blockIdx.x * 32, by = blockIdx.y * 32;
    int tx = threadIdx.x & 31, ty = threadIdx.x >> 5;
#pragma unroll
    for (int i = 0; i < 32; i += 8)
        t[ty + i][tx] = in[(size_t)(by + ty + i) * C + bx + tx];
    __syncthreads();
#pragma unroll
    for (int i = 0; i < 32; i += 8)
        out[(size_t)(bx + ty + i) * R + by + tx] = tf32_rna(t[tx][ty + i]);
}
__global__ void qp_k(const float* __restrict__ th, const float* __restrict__ wre,
                     const float* __restrict__ wim, float* __restrict__ qp) {
    int i = blockIdx.x * blockDim.x + threadIdx.x;
    if (i < DFF) {
        float s, c; sincosf(th[i], &s, &c);
        qp[i] = (c * wre[i] + s * wim[i]) * 0.1f;
    }
}

// ---------------- tf32 mma.sync GEMM:  C[M,N] = A[M,K] @ Bt[N,K]^T + epilogue ----------------
// CTA tile 128x128xBK32, 8 warps (2 m x 4 n), warp tile 64x32, mma m16n8k8.
#define BM 128
#define BN 128
#define BK 32
#define NSTAGE 3
#define STAGE_BYTES ((BM + BN) * BK * 4)        // 32768
#define SMEM_BYTES (NSTAGE * STAGE_BYTES)       // 98304

template <int KCHUNKS, bool FUSE_Q>
__global__ void __launch_bounds__(256)
tf32_gemm(const float* __restrict__ A, const float* __restrict__ Bt,
          const float* __restrict__ bias,
          const float* __restrict__ theta, const float* __restrict__ wim,
          const float* __restrict__ qp,
          float* __restrict__ C, int Kdim, int Ndim)
{
    extern __shared__ char smem[];
    const uint32_t sb = smem_u32(smem);
    const int tid = threadIdx.x;
    const int wid = tid >> 5, lid = tid & 31;
    const int wm = wid & 1, wn = wid >> 1;            // warp grid 2 x 4

    const int tile_n = blockIdx.x, tile_m = blockIdx.y;
    const float* Ab = A  + (size_t)tile_m * BM * Kdim;
    const float* Bb = Bt + (size_t)tile_n * BN * Kdim;

    float acc[4][4][4];                                // [mt][nt][4 c-regs]
#pragma unroll
    for (int i = 0; i < 4; i++)
#pragma unroll
        for (int j = 0; j < 4; j++)
#pragma unroll
            for (int q = 0; q < 4; q++) acc[i][j][q] = 0.0f;

    // ---- stage loader: A (128x32) then B (128x32), SW128-swizzled 16B chunks ----
    auto load_chunk = [&](int c, int s) {
        const uint32_t a_s = sb + s * STAGE_BYTES;
        const uint32_t b_s = a_s + BM * BK * 4;
        const float* ag = Ab + c * BK;
        const float* bg = Bb + c * BK;
#pragma unroll
        for (int i = 0; i < 4; i++) {
            int f = tid + i * 256;                     // 0..1023
            int r = f >> 3, kc = f & 7;
            uint32_t bo = (uint32_t)(r * 128 + kc * 16);
            cp_async16(a_s + sw128(bo), ag + (size_t)r * Kdim + kc * 4);
        }
#pragma unroll
        for (int i = 0; i < 4; i++) {
            int f = tid + i * 256;
            int r = f >> 3, kc = f & 7;
            uint32_t bo = (uint32_t)(r * 128 + kc * 16);
            cp_async16(b_s + sw128(bo), bg + (size_t)r * Kdim + kc * 4);
        }
    };

    // prologue: stages 0,1
#pragma unroll
    for (int c = 0; c < NSTAGE - 1; c++) {
        load_chunk(c, c);
        asm volatile("cp.async.commit_group;" ::: "memory");
    }

    // precomputed ldmatrix lane-address components (constant across iters except stage base)
    // A: per m-tile: row = wm*64 + mt*16 + ((lid>>3)&1)*8 + (lid&7); byte = ks*32 + ((lid>>4)&1)*16
    const int a_row_base = wm * 64 + ((lid >> 3) & 1) * 8 + (lid & 7);
    const int a_byte     = ((lid >> 4) & 1) * 16;
    // B: per n-pair: row = wn*32 + np*16 + ((lid>>4)&1)*8 + (lid&7); byte = ks*32 + ((lid>>3)&1)*16
    const int b_row_base = wn * 32 + ((lid >> 4) & 1) * 8 + (lid & 7);
    const int b_byte     = ((lid >> 3) & 1) * 16;

    for (int c = 0; c < KCHUNKS; c++) {
        asm volatile("cp.async.wait_group %0;" :: "n"(NSTAGE - 2));  // stage c resident
        __syncthreads();                                             // + iter c-1 compute done

        {   // issue loads for stage c+2 (overwrites stage computed at iter c-1)
            const int lc = c + NSTAGE - 1;
            if (lc < KCHUNKS) load_chunk(lc, lc % NSTAGE);
            asm volatile("cp.async.commit_group;" ::: "memory");
        }

        // ---- compute on stage c ----
        const uint32_t a_s = sb + (c % NSTAGE) * STAGE_BYTES;
        const uint32_t b_s = a_s + BM * BK * 4;
#pragma unroll
        for (int ks = 0; ks < 4; ks++) {
            uint32_t af[4][4];
#pragma unroll
            for (int mt = 0; mt < 4; mt++) {
                uint32_t bo = (uint32_t)((a_row_base + mt * 16) * 128 + ks * 32 + a_byte);
                ldsm_x4(af[mt][0], af[mt][1], af[mt][2], af[mt][3], a_s + sw128(bo));
            }
            uint32_t bf[4][2];
#pragma unroll
            for (int np = 0; np < 2; np++) {
                uint32_t bo = (uint32_t)((b_row_base + np * 16) * 128 + ks * 32 + b_byte);
                uint32_t r0, r1, r2, r3;
                ldsm_x4(r0, r1, r2, r3, b_s + sw128(bo));
                bf[np * 2 + 0][0] = r0; bf[np * 2 + 0][1] = r1;
                bf[np * 2 + 1][0] = r2; bf[np * 2 + 1][1] = r3;
            }
#pragma unroll
            for (int mt = 0; mt < 4; mt++)
#pragma unroll
                for (int nt = 0; nt < 4; nt++)
                    mma_tf32(acc[mt][nt], af[mt], bf[nt]);
        }
    }

    // ---- epilogue: bias (+ quantum + relu + tf32 round for GEMM1), float2 stores ----
#pragma unroll
    for (int nt = 0; nt < 4; nt++) {
        const int n = tile_n * BN + wn * 32 + nt * 8 + (lid & 3) * 2;
        const float2 bb = *(const float2*)(bias + n);
        float2 th2 = {0.f, 0.f}, wi2 = {0.f, 0.f}, qp2 = {0.f, 0.f};
        if (FUSE_Q) {
            th2 = *(const float2*)(theta + n);
            wi2 = *(const float2*)(wim + n);
            qp2 = *(const float2*)(qp + n);
        }
#pragma unroll
        for (int mt = 0; mt < 4; mt++) {
#pragma unroll
            for (int h = 0; h < 2; h++) {
                const size_t row = (size_t)tile_m * BM + wm * 64 + mt * 16 + (lid >> 2) + h * 8;
                float v0 = acc[mt][nt][2 * h + 0] + bb.x;
                float v1 = acc[mt][nt][2 * h + 1] + bb.y;
                if (FUSE_Q) {
                    float im0 = wi2.x * __sinf(th2.x + v0 * 0.1f);
                    float im1 = wi2.y * __sinf(th2.y + v1 * 0.1f);
                    v0 = fmaf(qp2.x, im0, v0);
                    v1 = fmaf(qp2.y, im1, v1);
                    v0 = tf32_rna(fmaxf(v0, 0.0f));
                    v1 = tf32_rna(fmaxf(v1, 0.0f));
                }
                *(float2*)(C + row * Ndim + n) = make_float2(v0, v1);
            }
        }
    }
}

// ---------------- host entry ----------------
extern "C" void kernel_launch(void* const* d_in, const int* in_sizes, int n_in,
                              void* d_out, int out_size)
{
    const float* x   = (const float*)d_in[0];
    const float* W1  = (const float*)d_in[1];
    const float* b1  = (const float*)d_in[2];
    const float* th  = (const float*)d_in[3];
    const float* wre = (const float*)d_in[4];
    const float* wim = (const float*)d_in[5];
    const float* W2  = (const float*)d_in[6];
    const float* b2  = (const float*)d_in[7];
    float* out = (float*)d_out;

    void *pxr, *pw1t, *pw2t, *pact, *pqp;
    cudaGetSymbolAddress(&pxr,  g_xr);
    cudaGetSymbolAddress(&pw1t, g_w1t);
    cudaGetSymbolAddress(&pw2t, g_w2t);
    cudaGetSymbolAddress(&pact, g_act);
    cudaGetSymbolAddress(&pqp,  g_qp);
    float* xr  = (float*)pxr;
    float* w1t = (float*)pw1t;
    float* w2t = (float*)pw2t;
    float* act = (float*)pact;
    float* qp  = (float*)pqp;

    cudaFuncSetAttribute(tf32_gemm<DMODEL / BK, true>,
                         cudaFuncAttributeMaxDynamicSharedMemorySize, SMEM_BYTES);
    cudaFuncSetAttribute(tf32_gemm<DFF / BK, false>,
                         cudaFuncAttributeMaxDynamicSharedMemorySize, SMEM_BYTES);

    // preprocessing
    {
        int n4 = MTOK * DMODEL / 4;
        round_copy_k<<<(n4 + 255) / 256, 256>>>(x, xr, n4);
    }
    transpose_round_k<<<dim3(DFF / 32, DMODEL / 32), 256>>>(W1, w1t, DMODEL, DFF);
    transpose_round_k<<<dim3(DMODEL / 32, DFF / 32), 256>>>(W2, w2t, DFF, DMODEL);
    qp_k<<<DFF / 256, 256>>>(th, wre, wim, qp);

    // GEMM1: act = round_tf32(relu(qt(x @ W1 + b1)))   [8192, 4096]
    tf32_gemm<DMODEL / BK, true><<<dim3(DFF / BN, MTOK / BM), 256, SMEM_BYTES>>>(
        xr, w1t, b1, th, wim, qp, act, DMODEL, DFF);

    // GEMM2: out = act @ W2 + b2                        [8192, 1024]
    tf32_gemm<DFF / BK, false><<<dim3(DMODEL / BN, MTOK / BM), 256, SMEM_BYTES>>>(
        act, w2t, b2, nullptr, nullptr, nullptr, out, DFF, DMODEL);
}

// round 4
// speedup vs baseline: 6.5421x; 1.8498x over previous
#include <cuda_runtime.h>
#include <cuda_fp16.h>
#include <cstdint>
#include <math.h>

#define MTOK   8192
#define DMODEL 1024
#define DFF    4096

// ---------------- scratch (device globals; no runtime allocation) ----------------
__device__ __half g_xh [(size_t)MTOK * DMODEL];   // x in fp16
__device__ __half g_w1t[(size_t)DFF  * DMODEL];   // W1^T fp16  [N=4096][K=1024]
__device__ __half g_w2t[(size_t)DMODEL * DFF];    // W2^T fp16  [N=1024][K=4096]
__device__ __half g_act[(size_t)MTOK * DFF];      // post-activation hidden, fp16
__device__ float  g_qp [DFF];                     // (cos(th)*wre + sin(th)*wim)*0.1

// ---------------- helpers ----------------
__device__ __forceinline__ uint32_t smem_u32(const void* p) {
    uint32_t a;
    asm("{ .reg .u64 t; cvta.to.shared.u64 t, %1; cvt.u32.u64 %0, t; }" : "=r"(a) : "l"(p));
    return a;
}
__device__ __forceinline__ void cp_async16(uint32_t saddr, const void* g) {
    asm volatile("cp.async.cg.shared.global [%0], [%1], 16;" :: "r"(saddr), "l"(g) : "memory");
}
__device__ __forceinline__ void ldsm_x4(uint32_t& r0, uint32_t& r1, uint32_t& r2, uint32_t& r3,
                                        uint32_t addr) {
    asm volatile("ldmatrix.sync.aligned.m8n8.x4.shared.b16 {%0,%1,%2,%3}, [%4];"
                 : "=r"(r0), "=r"(r1), "=r"(r2), "=r"(r3) : "r"(addr));
}
__device__ __forceinline__ void mma_f16(float* c, const uint32_t* a, const uint32_t* b) {
    asm volatile(
        "mma.sync.aligned.m16n8k16.row.col.f32.f16.f16.f32 "
        "{%0,%1,%2,%3}, {%4,%5,%6,%7}, {%8,%9}, {%0,%1,%2,%3};"
        : "+f"(c[0]), "+f"(c[1]), "+f"(c[2]), "+f"(c[3])
        : "r"(a[0]), "r"(a[1]), "r"(a[2]), "r"(a[3]), "r"(b[0]), "r"(b[1]));
}
__device__ __forceinline__ uint32_t sw128(uint32_t bo) { return bo ^ ((bo >> 3) & 0x70); }

// ---------------- preprocessing kernels ----------------
// fp32 -> fp16 copy, 4 elems/thread
__global__ void to_half_k(const float* __restrict__ in, __half* __restrict__ out, int n4) {
    int i = blockIdx.x * blockDim.x + threadIdx.x;
    if (i < n4) {
        float4 v = ((const float4*)in)[i];
        __half2 h0 = __floats2half2_rn(v.x, v.y);
        __half2 h1 = __floats2half2_rn(v.z, v.w);
        uint2 o;
        o.x = *(uint32_t*)&h0;
        o.y = *(uint32_t*)&h1;
        ((uint2*)out)[i] = o;
    }
}
// in[R][C] fp32 -> out[C][R] fp16
__global__ void transpose_half_k(const float* __restrict__ in, __half* __restrict__ out,
                                 int R, int C) {
    __shared__ float t[32][33];
    int bx = blockIdx.x * 32, by = blockIdx.y * 32;
    int tx = threadIdx.x & 31, ty = threadIdx.x >> 5;
#pragma unroll
    for (int i = 0; i < 32; i += 8)
        t[ty + i][tx] = in[(size_t)(by + ty + i) * C + bx + tx];
    __syncthreads();
#pragma unroll
    for (int i = 0; i < 32; i += 8)
        out[(size_t)(bx + ty + i) * R + by + tx] = __float2half_rn(t[tx][ty + i]);
}
__global__ void qp_k(const float* __restrict__ th, const float* __restrict__ wre,
                     const float* __restrict__ wim, float* __restrict__ qp) {
    int i = blockIdx.x * blockDim.x + threadIdx.x;
    if (i < DFF) {
        float s, c; sincosf(th[i], &s, &c);
        qp[i] = (c * wre[i] + s * wim[i]) * 0.1f;
    }
}

// ---------------- fp16 mma.sync GEMM:  C[M,N] = A[M,K] @ Bt[N,K]^T + epilogue ----------------
// CTA tile 128x128 x BK64(halfs), 8 warps (2m x 4n), warp tile 64x32, mma m16n8k16.
// smem rows: 64 halfs = 128B -> SW128 swizzle, 16B chunks.
#define BM 128
#define BN 128
#define BK 64
#define NSTAGE 3
#define STAGE_BYTES ((BM + BN) * BK * 2)        // 32768
#define SMEM_BYTES (NSTAGE * STAGE_BYTES)       // 98304

// FUSE_Q=true: OutT=__half (writes fp16 act). FUSE_Q=false: OutT=float (final output).
template <int KCHUNKS, bool FUSE_Q, typename OutT>
__global__ void __launch_bounds__(256)
h16_gemm(const __half* __restrict__ A, const __half* __restrict__ Bt,
         const float* __restrict__ bias,
         const float* __restrict__ theta, const float* __restrict__ wim,
         const float* __restrict__ qp,
         OutT* __restrict__ C, int Kdim, int Ndim)
{
    extern __shared__ char smem[];
    const uint32_t sb = smem_u32(smem);
    const int tid = threadIdx.x;
    const int wid = tid >> 5, lid = tid & 31;
    const int wm = wid & 1, wn = wid >> 1;            // warp grid 2 x 4

    const int tile_n = blockIdx.x, tile_m = blockIdx.y;
    const __half* Ab = A  + (size_t)tile_m * BM * Kdim;
    const __half* Bb = Bt + (size_t)tile_n * BN * Kdim;

    float acc[4][4][4];
#pragma unroll
    for (int i = 0; i < 4; i++)
#pragma unroll
        for (int j = 0; j < 4; j++)
#pragma unroll
            for (int q = 0; q < 4; q++) acc[i][j][q] = 0.0f;

    // ---- stage loader: A (128 rows x 64 halfs) then B, SW128-swizzled 16B chunks ----
    auto load_chunk = [&](int c, int s) {
        const uint32_t a_s = sb + s * STAGE_BYTES;
        const uint32_t b_s = a_s + BM * BK * 2;
        const __half* ag = Ab + c * BK;
        const __half* bg = Bb + c * BK;
#pragma unroll
        for (int i = 0; i < 4; i++) {
            int f = tid + i * 256;                     // 0..1023
            int r = f >> 3, kc = f & 7;                // row, 16B chunk (8 halfs)
            uint32_t bo = (uint32_t)(r * 128 + kc * 16);
            cp_async16(a_s + sw128(bo), ag + (size_t)r * Kdim + kc * 8);
        }
#pragma unroll
        for (int i = 0; i < 4; i++) {
            int f = tid + i * 256;
            int r = f >> 3, kc = f & 7;
            uint32_t bo = (uint32_t)(r * 128 + kc * 16);
            cp_async16(b_s + sw128(bo), bg + (size_t)r * Kdim + kc * 8);
        }
    };

#pragma unroll
    for (int c = 0; c < NSTAGE - 1; c++) {
        load_chunk(c, c);
        asm volatile("cp.async.commit_group;" ::: "memory");
    }

    // ldmatrix lane-address components (verified fragment geometry from round 3)
    const int a_row_base = wm * 64 + ((lid >> 3) & 1) * 8 + (lid & 7);
    const int a_byte     = ((lid >> 4) & 1) * 16;
    const int b_row_base = wn * 32 + ((lid >> 4) & 1) * 8 + (lid & 7);
    const int b_byte     = ((lid >> 3) & 1) * 16;

    for (int c = 0; c < KCHUNKS; c++) {
        asm volatile("cp.async.wait_group %0;" :: "n"(NSTAGE - 2));
        __syncthreads();

        {
            const int lc = c + NSTAGE - 1;
            if (lc < KCHUNKS) load_chunk(lc, lc % NSTAGE);
            asm volatile("cp.async.commit_group;" ::: "memory");
        }

        const uint32_t a_s = sb + (c % NSTAGE) * STAGE_BYTES;
        const uint32_t b_s = a_s + BM * BK * 2;
#pragma unroll
        for (int ks = 0; ks < 4; ks++) {               // 4 x k16 = BK 64
            uint32_t af[4][4];
#pragma unroll
            for (int mt = 0; mt < 4; mt++) {
                uint32_t bo = (uint32_t)((a_row_base + mt * 16) * 128 + ks * 32 + a_byte);
                ldsm_x4(af[mt][0], af[mt][1], af[mt][2], af[mt][3], a_s + sw128(bo));
            }
            uint32_t bf[4][2];
#pragma unroll
            for (int np = 0; np < 2; np++) {
                uint32_t bo = (uint32_t)((b_row_base + np * 16) * 128 + ks * 32 + b_byte);
                uint32_t r0, r1, r2, r3;
                ldsm_x4(r0, r1, r2, r3, b_s + sw128(bo));
                bf[np * 2 + 0][0] = r0; bf[np * 2 + 0][1] = r1;
                bf[np * 2 + 1][0] = r2; bf[np * 2 + 1][1] = r3;
            }
#pragma unroll
            for (int mt = 0; mt < 4; mt++)
#pragma unroll
                for (int nt = 0; nt < 4; nt++)
                    mma_f16(acc[mt][nt], af[mt], bf[nt]);
        }
    }

    // ---- epilogue ----
#pragma unroll
    for (int nt = 0; nt < 4; nt++) {
        const int n = tile_n * BN + wn * 32 + nt * 8 + (lid & 3) * 2;
        const float2 bb = *(const float2*)(bias + n);
        float2 th2 = {0.f, 0.f}, wi2 = {0.f, 0.f}, qp2 = {0.f, 0.f};
        if (FUSE_Q) {
            th2 = *(const float2*)(theta + n);
            wi2 = *(const float2*)(wim + n);
            qp2 = *(const float2*)(qp + n);
        }
#pragma unroll
        for (int mt = 0; mt < 4; mt++) {
#pragma unroll
            for (int h = 0; h < 2; h++) {
                const size_t row = (size_t)tile_m * BM + wm * 64 + mt * 16 + (lid >> 2) + h * 8;
                float v0 = acc[mt][nt][2 * h + 0] + bb.x;
                float v1 = acc[mt][nt][2 * h + 1] + bb.y;
                if (FUSE_Q) {
                    float im0 = wi2.x * __sinf(th2.x + v0 * 0.1f);
                    float im1 = wi2.y * __sinf(th2.y + v1 * 0.1f);
                    v0 = fmaf(qp2.x, im0, v0);
                    v1 = fmaf(qp2.y, im1, v1);
                    v0 = fmaxf(v0, 0.0f);
                    v1 = fmaxf(v1, 0.0f);
                }
                if (FUSE_Q) {
                    __half2 hv = __floats2half2_rn(v0, v1);
                    *(__half2*)((__half*)C + row * Ndim + n) = hv;
                } else {
                    *(float2*)((float*)C + row * Ndim + n) = make_float2(v0, v1);
                }
            }
        }
    }
}

// ---------------- host entry ----------------
extern "C" void kernel_launch(void* const* d_in, const int* in_sizes, int n_in,
                              void* d_out, int out_size)
{
    const float* x   = (const float*)d_in[0];
    const float* W1  = (const float*)d_in[1];
    const float* b1  = (const float*)d_in[2];
    const float* th  = (const float*)d_in[3];
    const float* wre = (const float*)d_in[4];
    const float* wim = (const float*)d_in[5];
    const float* W2  = (const float*)d_in[6];
    const float* b2  = (const float*)d_in[7];
    float* out = (float*)d_out;

    void *pxh, *pw1t, *pw2t, *pact, *pqp;
    cudaGetSymbolAddress(&pxh,  g_xh);
    cudaGetSymbolAddress(&pw1t, g_w1t);
    cudaGetSymbolAddress(&pw2t, g_w2t);
    cudaGetSymbolAddress(&pact, g_act);
    cudaGetSymbolAddress(&pqp,  g_qp);
    __half* xh  = (__half*)pxh;
    __half* w1t = (__half*)pw1t;
    __half* w2t = (__half*)pw2t;
    __half* act = (__half*)pact;
    float*  qp  = (float*)pqp;

    cudaFuncSetAttribute((const void*)h16_gemm<DMODEL / BK, true, __half>,
                         cudaFuncAttributeMaxDynamicSharedMemorySize, SMEM_BYTES);
    cudaFuncSetAttribute((const void*)h16_gemm<DFF / BK, false, float>,
                         cudaFuncAttributeMaxDynamicSharedMemorySize, SMEM_BYTES);

    // preprocessing: x->fp16; W1^T, W2^T -> fp16; per-channel quantum phase
    {
        int n4 = MTOK * DMODEL / 4;
        to_half_k<<<(n4 + 255) / 256, 256>>>(x, xh, n4);
    }
    transpose_half_k<<<dim3(DFF / 32, DMODEL / 32), 256>>>(W1, w1t, DMODEL, DFF);
    transpose_half_k<<<dim3(DMODEL / 32, DFF / 32), 256>>>(W2, w2t, DFF, DMODEL);
    qp_k<<<DFF / 256, 256>>>(th, wre, wim, qp);

    // GEMM1: act = fp16(relu(qt(x @ W1 + b1)))   [8192, 4096]
    h16_gemm<DMODEL / BK, true, __half><<<dim3(DFF / BN, MTOK / BM), 256, SMEM_BYTES>>>(
        xh, w1t, b1, th, wim, qp, act, DMODEL, DFF);

    // GEMM2: out = act @ W2 + b2                  [8192, 1024]
    h16_gemm<DFF / BK, false, float><<<dim3(DMODEL / BN, MTOK / BM), 256, SMEM_BYTES>>>(
        act, w2t, b2, nullptr, nullptr, nullptr, out, DFF, DMODEL);
}

// round 5
// speedup vs baseline: 7.7485x; 1.1844x over previous
#include <cuda_runtime.h>
#include <cuda_fp16.h>
#include <cstdint>
#include <math.h>

#define MTOK   8192
#define DMODEL 1024
#define DFF    4096

// ---------------- scratch (device globals; no runtime allocation) ----------------
__device__ __half g_xh [(size_t)MTOK * DMODEL];   // x in fp16
__device__ __half g_w1t[(size_t)DFF  * DMODEL];   // W1^T fp16  [N=4096][K=1024]
__device__ __half g_w2t[(size_t)DMODEL * DFF];    // W2^T fp16  [N=1024][K=4096]
__device__ __half g_act[(size_t)MTOK * DFF];      // post-activation hidden, fp16
__device__ float  g_qp [DFF];                     // (cos(th)*wre + sin(th)*wim)*0.1

// ---------------- helpers ----------------
__device__ __forceinline__ uint32_t smem_u32(const void* p) {
    uint32_t a;
    asm("{ .reg .u64 t; cvta.to.shared.u64 t, %1; cvt.u32.u64 %0, t; }" : "=r"(a) : "l"(p));
    return a;
}
__device__ __forceinline__ void cp_async16(uint32_t saddr, const void* g) {
    asm volatile("cp.async.cg.shared.global [%0], [%1], 16;" :: "r"(saddr), "l"(g) : "memory");
}
__device__ __forceinline__ void ldsm_x4(uint32_t& r0, uint32_t& r1, uint32_t& r2, uint32_t& r3,
                                        uint32_t addr) {
    asm volatile("ldmatrix.sync.aligned.m8n8.x4.shared.b16 {%0,%1,%2,%3}, [%4];"
                 : "=r"(r0), "=r"(r1), "=r"(r2), "=r"(r3) : "r"(addr));
}
__device__ __forceinline__ void mma_f16(float* c, const uint32_t* a, const uint32_t* b) {
    asm volatile(
        "mma.sync.aligned.m16n8k16.row.col.f32.f16.f16.f32 "
        "{%0,%1,%2,%3}, {%4,%5,%6,%7}, {%8,%9}, {%0,%1,%2,%3};"
        : "+f"(c[0]), "+f"(c[1]), "+f"(c[2]), "+f"(c[3])
        : "r"(a[0]), "r"(a[1]), "r"(a[2]), "r"(a[3]), "r"(b[0]), "r"(b[1]));
}
__device__ __forceinline__ uint32_t sw128(uint32_t bo) { return bo ^ ((bo >> 3) & 0x70); }

// ---------------- preprocessing kernels ----------------
__global__ void to_half_k(const float* __restrict__ in, __half* __restrict__ out, int n4) {
    int i = blockIdx.x * blockDim.x + threadIdx.x;
    if (i < n4) {
        float4 v = ((const float4*)in)[i];
        __half2 h0 = __floats2half2_rn(v.x, v.y);
        __half2 h1 = __floats2half2_rn(v.z, v.w);
        uint2 o;
        o.x = *(uint32_t*)&h0;
        o.y = *(uint32_t*)&h1;
        ((uint2*)out)[i] = o;
    }
}
__global__ void transpose_half_k(const float* __restrict__ in, __half* __restrict__ out,
                                 int R, int C) {
    __shared__ float t[32][33];
    int bx = blockIdx.x * 32, by = blockIdx.y * 32;
    int tx = threadIdx.x & 31, ty = threadIdx.x >> 5;
#pragma unroll
    for (int i = 0; i < 32; i += 8)
        t[ty + i][tx] = in[(size_t)(by + ty + i) * C + bx + tx];
    __syncthreads();
#pragma unroll
    for (int i = 0; i < 32; i += 8)
        out[(size_t)(bx + ty + i) * R + by + tx] = __float2half_rn(t[tx][ty + i]);
}
__global__ void qp_k(const float* __restrict__ th, const float* __restrict__ wre,
                     const float* __restrict__ wim, float* __restrict__ qp) {
    int i = blockIdx.x * blockDim.x + threadIdx.x;
    if (i < DFF) {
        float s, c; sincosf(th[i], &s, &c);
        qp[i] = (c * wre[i] + s * wim[i]) * 0.1f;
    }
}

// ---------------- fp16 mma.sync GEMM:  C[M,N] = A[M,K] @ Bt[N,K]^T + epilogue ----------------
// CTA tile 128(M) x 256(N) x BK64(halfs), 8 warps (2m x 4n), warp tile 64x64, mma m16n8k16.
// smem rows: 64 halfs = 128B -> SW128 swizzle, 16B chunks. 3 stages = 147456 B.
#define BM 128
#define BN 256
#define BK 64
#define NSTAGE 3
#define A_BYTES (BM * BK * 2)                   // 16384
#define STAGE_BYTES ((BM + BN) * BK * 2)        // 49152
#define SMEM_BYTES (NSTAGE * STAGE_BYTES)       // 147456

template <int KCHUNKS, bool FUSE_Q, typename OutT>
__global__ void __launch_bounds__(256, 1)
h16_gemm(const __half* __restrict__ A, const __half* __restrict__ Bt,
         const float* __restrict__ bias,
         const float* __restrict__ theta, const float* __restrict__ wim,
         const float* __restrict__ qp,
         OutT* __restrict__ C, int Kdim, int Ndim)
{
    extern __shared__ char smem[];
    const uint32_t sb = smem_u32(smem);
    const int tid = threadIdx.x;
    const int wid = tid >> 5, lid = tid & 31;
    const int wm = wid & 1, wn = wid >> 1;            // warp grid 2(m) x 4(n)

    const int tile_n = blockIdx.x, tile_m = blockIdx.y;
    const __half* Ab = A  + (size_t)tile_m * BM * Kdim;
    const __half* Bb = Bt + (size_t)tile_n * BN * Kdim;

    float acc[4][8][4];                                // [mt][nt][4]
#pragma unroll
    for (int i = 0; i < 4; i++)
#pragma unroll
        for (int j = 0; j < 8; j++)
#pragma unroll
            for (int q = 0; q < 4; q++) acc[i][j][q] = 0.0f;

    // ---- stage loader: A 128 rows + B 256 rows, each 64 halfs (128B), swizzled 16B chunks ----
    auto load_chunk = [&](int c, int s) {
        const uint32_t a_s = sb + s * STAGE_BYTES;
        const uint32_t b_s = a_s + A_BYTES;
        const __half* ag = Ab + c * BK;
        const __half* bg = Bb + c * BK;
#pragma unroll
        for (int i = 0; i < 4; i++) {                  // A: 128 rows x 8 chunks = 1024
            int f = tid + i * 256;
            int r = f >> 3, kc = f & 7;
            uint32_t bo = (uint32_t)(r * 128 + kc * 16);
            cp_async16(a_s + sw128(bo), ag + (size_t)r * Kdim + kc * 8);
        }
#pragma unroll
        for (int i = 0; i < 8; i++) {                  // B: 256 rows x 8 chunks = 2048
            int f = tid + i * 256;
            int r = f >> 3, kc = f & 7;
            uint32_t bo = (uint32_t)(r * 128 + kc * 16);
            cp_async16(b_s + sw128(bo), bg + (size_t)r * Kdim + kc * 8);
        }
    };

#pragma unroll
    for (int c = 0; c < NSTAGE - 1; c++) {
        load_chunk(c, c);
        asm volatile("cp.async.commit_group;" ::: "memory");
    }

    // ldmatrix lane-address components (same verified geometry)
    const int a_row_base = wm * 64 + ((lid >> 3) & 1) * 8 + (lid & 7);
    const int a_byte     = ((lid >> 4) & 1) * 16;
    const int b_row_base = wn * 64 + ((lid >> 4) & 1) * 8 + (lid & 7);
    const int b_byte     = ((lid >> 3) & 1) * 16;

    for (int c = 0; c < KCHUNKS; c++) {
        asm volatile("cp.async.wait_group %0;" :: "n"(NSTAGE - 2));
        __syncthreads();

        {
            const int lc = c + NSTAGE - 1;
            if (lc < KCHUNKS) load_chunk(lc, lc % NSTAGE);
            asm volatile("cp.async.commit_group;" ::: "memory");
        }

        const uint32_t a_s = sb + (c % NSTAGE) * STAGE_BYTES;
        const uint32_t b_s = a_s + A_BYTES;
#pragma unroll
        for (int ks = 0; ks < 4; ks++) {               // 4 x k16 = BK 64
            uint32_t af[4][4];
#pragma unroll
            for (int mt = 0; mt < 4; mt++) {
                uint32_t bo = (uint32_t)((a_row_base + mt * 16) * 128 + ks * 32 + a_byte);
                ldsm_x4(af[mt][0], af[mt][1], af[mt][2], af[mt][3], a_s + sw128(bo));
            }
            uint32_t bf[8][2];
#pragma unroll
            for (int np = 0; np < 4; np++) {           // each x4 covers 2 n-tiles (n16 x k16)
                uint32_t bo = (uint32_t)((b_row_base + np * 16) * 128 + ks * 32 + b_byte);
                uint32_t r0, r1, r2, r3;
                ldsm_x4(r0, r1, r2, r3, b_s + sw128(bo));
                bf[np * 2 + 0][0] = r0; bf[np * 2 + 0][1] = r1;
                bf[np * 2 + 1][0] = r2; bf[np * 2 + 1][1] = r3;
            }
#pragma unroll
            for (int mt = 0; mt < 4; mt++)
#pragma unroll
                for (int nt = 0; nt < 8; nt++)
                    mma_f16(acc[mt][nt], af[mt], bf[nt]);
        }
    }

    // ---- epilogue ----
#pragma unroll
    for (int nt = 0; nt < 8; nt++) {
        const int n = tile_n * BN + wn * 64 + nt * 8 + (lid & 3) * 2;
        const float2 bb = *(const float2*)(bias + n);
        float2 th2 = {0.f, 0.f}, wi2 = {0.f, 0.f}, qp2 = {0.f, 0.f};
        if (FUSE_Q) {
            th2 = *(const float2*)(theta + n);
            wi2 = *(const float2*)(wim + n);
            qp2 = *(const float2*)(qp + n);
        }
#pragma unroll
        for (int mt = 0; mt < 4; mt++) {
#pragma unroll
            for (int h = 0; h < 2; h++) {
                const size_t row = (size_t)tile_m * BM + wm * 64 + mt * 16 + (lid >> 2) + h * 8;
                float v0 = acc[mt][nt][2 * h + 0] + bb.x;
                float v1 = acc[mt][nt][2 * h + 1] + bb.y;
                if (FUSE_Q) {
                    float im0 = wi2.x * __sinf(th2.x + v0 * 0.1f);
                    float im1 = wi2.y * __sinf(th2.y + v1 * 0.1f);
                    v0 = fmaf(qp2.x, im0, v0);
                    v1 = fmaf(qp2.y, im1, v1);
                    v0 = fmaxf(v0, 0.0f);
                    v1 = fmaxf(v1, 0.0f);
                }
                if (FUSE_Q) {
                    __half2 hv = __floats2half2_rn(v0, v1);
                    *(__half2*)((__half*)C + row * Ndim + n) = hv;
                } else {
                    *(float2*)((float*)C + row * Ndim + n) = make_float2(v0, v1);
                }
            }
        }
    }
}

// ---------------- host entry ----------------
extern "C" void kernel_launch(void* const* d_in, const int* in_sizes, int n_in,
                              void* d_out, int out_size)
{
    const float* x   = (const float*)d_in[0];
    const float* W1  = (const float*)d_in[1];
    const float* b1  = (const float*)d_in[2];
    const float* th  = (const float*)d_in[3];
    const float* wre = (const float*)d_in[4];
    const float* wim = (const float*)d_in[5];
    const float* W2  = (const float*)d_in[6];
    const float* b2  = (const float*)d_in[7];
    float* out = (float*)d_out;

    void *pxh, *pw1t, *pw2t, *pact, *pqp;
    cudaGetSymbolAddress(&pxh,  g_xh);
    cudaGetSymbolAddress(&pw1t, g_w1t);
    cudaGetSymbolAddress(&pw2t, g_w2t);
    cudaGetSymbolAddress(&pact, g_act);
    cudaGetSymbolAddress(&pqp,  g_qp);
    __half* xh  = (__half*)pxh;
    __half* w1t = (__half*)pw1t;
    __half* w2t = (__half*)pw2t;
    __half* act = (__half*)pact;
    float*  qp  = (float*)pqp;

    cudaFuncSetAttribute((const void*)h16_gemm<DMODEL / BK, true, __half>,
                         cudaFuncAttributeMaxDynamicSharedMemorySize, SMEM_BYTES);
    cudaFuncSetAttribute((const void*)h16_gemm<DFF / BK, false, float>,
                         cudaFuncAttributeMaxDynamicSharedMemorySize, SMEM_BYTES);

    // preprocessing: x->fp16; W1^T, W2^T -> fp16; per-channel quantum phase
    {
        int n4 = MTOK * DMODEL / 4;
        to_half_k<<<(n4 + 255) / 256, 256>>>(x, xh, n4);
    }
    transpose_half_k<<<dim3(DFF / 32, DMODEL / 32), 256>>>(W1, w1t, DMODEL, DFF);
    transpose_half_k<<<dim3(DMODEL / 32, DFF / 32), 256>>>(W2, w2t, DFF, DMODEL);
    qp_k<<<DFF / 256, 256>>>(th, wre, wim, qp);

    // GEMM1: act = fp16(relu(qt(x @ W1 + b1)))   [8192, 4096], grid (16, 64)
    h16_gemm<DMODEL / BK, true, __half><<<dim3(DFF / BN, MTOK / BM), 256, SMEM_BYTES>>>(
        xh, w1t, b1, th, wim, qp, act, DMODEL, DFF);

    // GEMM2: out = act @ W2 + b2                  [8192, 1024], grid (4, 64)
    h16_gemm<DFF / BK, false, float><<<dim3(DMODEL / BN, MTOK / BM), 256, SMEM_BYTES>>>(
        act, w2t, b2, nullptr, nullptr, nullptr, out, DFF, DMODEL);
}

// round 6
// speedup vs baseline: 7.9325x; 1.0238x over previous
#include <cuda_runtime.h>
#include <cuda_fp16.h>
#include <cstdint>
#include <math.h>

#define MTOK   8192
#define DMODEL 1024
#define DFF    4096

// ---------------- scratch (device globals; no runtime allocation) ----------------
__device__ __half g_xh [(size_t)MTOK * DMODEL];   // x in fp16
__device__ __half g_w1t[(size_t)DFF  * DMODEL];   // W1^T fp16  [N=4096][K=1024]
__device__ __half g_w2t[(size_t)DMODEL * DFF];    // W2^T fp16  [N=1024][K=4096]
__device__ __half g_act[(size_t)MTOK * DFF];      // post-activation hidden, fp16
__device__ float  g_qp [DFF];                     // (cos(th)*wre + sin(th)*wim)*0.1

// ---------------- helpers ----------------
__device__ __forceinline__ uint32_t smem_u32(const void* p) {
    uint32_t a;
    asm("{ .reg .u64 t; cvta.to.shared.u64 t, %1; cvt.u32.u64 %0, t; }" : "=r"(a) : "l"(p));
    return a;
}
__device__ __forceinline__ void cp_async16(uint32_t saddr, const void* g) {
    asm volatile("cp.async.cg.shared.global [%0], [%1], 16;" :: "r"(saddr), "l"(g) : "memory");
}
__device__ __forceinline__ void ldsm_x4(uint32_t& r0, uint32_t& r1, uint32_t& r2, uint32_t& r3,
                                        uint32_t addr) {
    asm volatile("ldmatrix.sync.aligned.m8n8.x4.shared.b16 {%0,%1,%2,%3}, [%4];"
                 : "=r"(r0), "=r"(r1), "=r"(r2), "=r"(r3) : "r"(addr));
}
__device__ __forceinline__ void mma_f16(float* c, const uint32_t* a, const uint32_t* b) {
    asm volatile(
        "mma.sync.aligned.m16n8k16.row.col.f32.f16.f16.f32 "
        "{%0,%1,%2,%3}, {%4,%5,%6,%7}, {%8,%9}, {%0,%1,%2,%3};"
        : "+f"(c[0]), "+f"(c[1]), "+f"(c[2]), "+f"(c[3])
        : "r"(a[0]), "r"(a[1]), "r"(a[2]), "r"(a[3]), "r"(b[0]), "r"(b[1]));
}
__device__ __forceinline__ uint32_t sw128(uint32_t bo) { return bo ^ ((bo >> 3) & 0x70); }

// ---------------- preprocessing kernels ----------------
// Merged: blocks [0, XB) convert x fp32->fp16 (4 elem/thread); blocks [XB, XB+16) compute qp.
#define PREP_XB (MTOK * DMODEL / 4 / 256)   // 8192 blocks for x
__global__ void prep_k(const float* __restrict__ x, __half* __restrict__ xh,
                       const float* __restrict__ th, const float* __restrict__ wre,
                       const float* __restrict__ wim, float* __restrict__ qp) {
    int b = blockIdx.x;
    if (b < PREP_XB) {
        int i = b * 256 + threadIdx.x;
        float4 v = ((const float4*)x)[i];
        __half2 h0 = __floats2half2_rn(v.x, v.y);
        __half2 h1 = __floats2half2_rn(v.z, v.w);
        uint2 o;
        o.x = *(uint32_t*)&h0;
        o.y = *(uint32_t*)&h1;
        ((uint2*)xh)[i] = o;
    } else {
        int i = (b - PREP_XB) * 256 + threadIdx.x;
        if (i < DFF) {
            float s, c; sincosf(th[i], &s, &c);
            qp[i] = (c * wre[i] + s * wim[i]) * 0.1f;
        }
    }
}
// in[R][C] fp32 -> out[C][R] fp16
__global__ void transpose_half_k(const float* __restrict__ in, __half* __restrict__ out,
                                 int R, int C) {
    __shared__ float t[32][33];
    int bx = blockIdx.x * 32, by = blockIdx.y * 32;
    int tx = threadIdx.x & 31, ty = threadIdx.x >> 5;
#pragma unroll
    for (int i = 0; i < 32; i += 8)
        t[ty + i][tx] = in[(size_t)(by + ty + i) * C + bx + tx];
    __syncthreads();
#pragma unroll
    for (int i = 0; i < 32; i += 8)
        out[(size_t)(bx + ty + i) * R + by + tx] = __float2half_rn(t[tx][ty + i]);
}

// ---------------- fp16 mma.sync GEMM:  C[M,N] = A[M,K] @ Bt[N,K]^T + epilogue ----------------
// CTA tile 128(M) x 256(N) x BK64(halfs), 8 warps (2m x 4n), warp tile 64x64, mma m16n8k16.
// smem rows: 64 halfs = 128B -> SW128 swizzle, 16B chunks. 4 stages = 196608 B.
#define BM 128
#define BN 256
#define BK 64
#define NSTAGE 4
#define A_BYTES (BM * BK * 2)                   // 16384
#define STAGE_BYTES ((BM + BN) * BK * 2)        // 49152
#define SMEM_BYTES (NSTAGE * STAGE_BYTES)       // 196608

template <int KCHUNKS, bool FUSE_Q, typename OutT>
__global__ void __launch_bounds__(256, 1)
h16_gemm(const __half* __restrict__ A, const __half* __restrict__ Bt,
         const float* __restrict__ bias,
         const float* __restrict__ theta, const float* __restrict__ wim,
         const float* __restrict__ qp,
         OutT* __restrict__ C, int Kdim, int Ndim)
{
    extern __shared__ char smem[];
    const uint32_t sb = smem_u32(smem);
    const int tid = threadIdx.x;
    const int wid = tid >> 5, lid = tid & 31;
    const int wm = wid & 1, wn = wid >> 1;            // warp grid 2(m) x 4(n)

    const int tile_n = blockIdx.x, tile_m = blockIdx.y;
    const __half* Ab = A  + (size_t)tile_m * BM * Kdim;
    const __half* Bb = Bt + (size_t)tile_n * BN * Kdim;

    float acc[4][8][4];                                // [mt][nt][4]
#pragma unroll
    for (int i = 0; i < 4; i++)
#pragma unroll
        for (int j = 0; j < 8; j++)
#pragma unroll
            for (int q = 0; q < 4; q++) acc[i][j][q] = 0.0f;

    // ---- stage loader: A 128 rows + B 256 rows, each 64 halfs (128B), swizzled 16B chunks ----
    auto load_chunk = [&](int c, int s) {
        const uint32_t a_s = sb + s * STAGE_BYTES;
        const uint32_t b_s = a_s + A_BYTES;
        const __half* ag = Ab + c * BK;
        const __half* bg = Bb + c * BK;
#pragma unroll
        for (int i = 0; i < 4; i++) {                  // A: 128 rows x 8 chunks = 1024
            int f = tid + i * 256;
            int r = f >> 3, kc = f & 7;
            uint32_t bo = (uint32_t)(r * 128 + kc * 16);
            cp_async16(a_s + sw128(bo), ag + (size_t)r * Kdim + kc * 8);
        }
#pragma unroll
        for (int i = 0; i < 8; i++) {                  // B: 256 rows x 8 chunks = 2048
            int f = tid + i * 256;
            int r = f >> 3, kc = f & 7;
            uint32_t bo = (uint32_t)(r * 128 + kc * 16);
            cp_async16(b_s + sw128(bo), bg + (size_t)r * Kdim + kc * 8);
        }
    };

#pragma unroll
    for (int c = 0; c < NSTAGE - 1; c++) {
        load_chunk(c, c);
        asm volatile("cp.async.commit_group;" ::: "memory");
    }

    // ldmatrix lane-address components (verified fragment geometry)
    const int a_row_base = wm * 64 + ((lid >> 3) & 1) * 8 + (lid & 7);
    const int a_byte     = ((lid >> 4) & 1) * 16;
    const int b_row_base = wn * 64 + ((lid >> 4) & 1) * 8 + (lid & 7);
    const int b_byte     = ((lid >> 3) & 1) * 16;

    for (int c = 0; c < KCHUNKS; c++) {
        // stage c resident: (NSTAGE-1)+c groups committed; <=NSTAGE-2 pending => chunks 0..c done
        asm volatile("cp.async.wait_group %0;" :: "n"(NSTAGE - 2));
        __syncthreads();

        {
            const int lc = c + NSTAGE - 1;
            if (lc < KCHUNKS) load_chunk(lc, lc & (NSTAGE - 1));
            asm volatile("cp.async.commit_group;" ::: "memory");   // empty group in tail keeps count
        }

        const uint32_t a_s = sb + (c & (NSTAGE - 1)) * STAGE_BYTES;
        const uint32_t b_s = a_s + A_BYTES;
#pragma unroll
        for (int ks = 0; ks < 4; ks++) {               // 4 x k16 = BK 64
            uint32_t af[4][4];
#pragma unroll
            for (int mt = 0; mt < 4; mt++) {
                uint32_t bo = (uint32_t)((a_row_base + mt * 16) * 128 + ks * 32 + a_byte);
                ldsm_x4(af[mt][0], af[mt][1], af[mt][2], af[mt][3], a_s + sw128(bo));
            }
            uint32_t bf[8][2];
#pragma unroll
            for (int np = 0; np < 4; np++) {           // each x4 covers 2 n-tiles (n16 x k16)
                uint32_t bo = (uint32_t)((b_row_base + np * 16) * 128 + ks * 32 + b_byte);
                uint32_t r0, r1, r2, r3;
                ldsm_x4(r0, r1, r2, r3, b_s + sw128(bo));
                bf[np * 2 + 0][0] = r0; bf[np * 2 + 0][1] = r1;
                bf[np * 2 + 1][0] = r2; bf[np * 2 + 1][1] = r3;
            }
#pragma unroll
            for (int mt = 0; mt < 4; mt++)
#pragma unroll
                for (int nt = 0; nt < 8; nt++)
                    mma_f16(acc[mt][nt], af[mt], bf[nt]);
        }
    }

    // ---- epilogue ----
#pragma unroll
    for (int nt = 0; nt < 8; nt++) {
        const int n = tile_n * BN + wn * 64 + nt * 8 + (lid & 3) * 2;
        const float2 bb = *(const float2*)(bias + n);
        float2 th2 = {0.f, 0.f}, wi2 = {0.f, 0.f}, qp2 = {0.f, 0.f};
        if (FUSE_Q) {
            th2 = *(const float2*)(theta + n);
            wi2 = *(const float2*)(wim + n);
            qp2 = *(const float2*)(qp + n);
        }
#pragma unroll
        for (int mt = 0; mt < 4; mt++) {
#pragma unroll
            for (int h = 0; h < 2; h++) {
                const size_t row = (size_t)tile_m * BM + wm * 64 + mt * 16 + (lid >> 2) + h * 8;
                float v0 = acc[mt][nt][2 * h + 0] + bb.x;
                float v1 = acc[mt][nt][2 * h + 1] + bb.y;
                if (FUSE_Q) {
                    float im0 = wi2.x * __sinf(th2.x + v0 * 0.1f);
                    float im1 = wi2.y * __sinf(th2.y + v1 * 0.1f);
                    v0 = fmaf(qp2.x, im0, v0);
                    v1 = fmaf(qp2.y, im1, v1);
                    v0 = fmaxf(v0, 0.0f);
                    v1 = fmaxf(v1, 0.0f);
                }
                if (FUSE_Q) {
                    __half2 hv = __floats2half2_rn(v0, v1);
                    *(__half2*)((__half*)C + row * Ndim + n) = hv;
                } else {
                    *(float2*)((float*)C + row * Ndim + n) = make_float2(v0, v1);
                }
            }
        }
    }
}

// ---------------- host entry ----------------
extern "C" void kernel_launch(void* const* d_in, const int* in_sizes, int n_in,
                              void* d_out, int out_size)
{
    const float* x   = (const float*)d_in[0];
    const float* W1  = (const float*)d_in[1];
    const float* b1  = (const float*)d_in[2];
    const float* th  = (const float*)d_in[3];
    const float* wre = (const float*)d_in[4];
    const float* wim = (const float*)d_in[5];
    const float* W2  = (const float*)d_in[6];
    const float* b2  = (const float*)d_in[7];
    float* out = (float*)d_out;

    void *pxh, *pw1t, *pw2t, *pact, *pqp;
    cudaGetSymbolAddress(&pxh,  g_xh);
    cudaGetSymbolAddress(&pw1t, g_w1t);
    cudaGetSymbolAddress(&pw2t, g_w2t);
    cudaGetSymbolAddress(&pact, g_act);
    cudaGetSymbolAddress(&pqp,  g_qp);
    __half* xh  = (__half*)pxh;
    __half* w1t = (__half*)pw1t;
    __half* w2t = (__half*)pw2t;
    __half* act = (__half*)pact;
    float*  qp  = (float*)pqp;

    cudaFuncSetAttribute((const void*)h16_gemm<DMODEL / BK, true, __half>,
                         cudaFuncAttributeMaxDynamicSharedMemorySize, SMEM_BYTES);
    cudaFuncSetAttribute((const void*)h16_gemm<DFF / BK, false, float>,
                         cudaFuncAttributeMaxDynamicSharedMemorySize, SMEM_BYTES);

    // preprocessing: x->fp16 + qp (merged); W1^T, W2^T -> fp16
    prep_k<<<PREP_XB + DFF / 256, 256>>>(x, xh, th, wre, wim, qp);
    transpose_half_k<<<dim3(DFF / 32, DMODEL / 32), 256>>>(W1, w1t, DMODEL, DFF);
    transpose_half_k<<<dim3(DMODEL / 32, DFF / 32), 256>>>(W2, w2t, DFF, DMODEL);

    // GEMM1: act = fp16(relu(qt(x @ W1 + b1)))   [8192, 4096], grid (16, 64)
    h16_gemm<DMODEL / BK, true, __half><<<dim3(DFF / BN, MTOK / BM), 256, SMEM_BYTES>>>(
        xh, w1t, b1, th, wim, qp, act, DMODEL, DFF);

    // GEMM2: out = act @ W2 + b2                  [8192, 1024], grid (4, 64)
    h16_gemm<DFF / BK, false, float><<<dim3(DMODEL / BN, MTOK / BM), 256, SMEM_BYTES>>>(
        act, w2t, b2, nullptr, nullptr, nullptr, out, DFF, DMODEL);
}